// round 10
// baseline (speedup 1.0000x reference)
#include <cuda_runtime.h>
#include <cuda_bf16.h>
#include <cstdint>

#define Nn 4096
#define NF 512
#define NH 64
#define H1 8
#define NC 16
#define WPR 128   // words per adjacency row (4096/32)

// ---------------- scratch (static device globals; no allocation) ----------------
__device__ __align__(16) unsigned g_adj[Nn * WPR];            // 2 MB bitmask
__device__ __align__(16) float g_feats1[H1 * Nn * NH];        // 8 MB  [h][i][f]
// g_ftb: MMA-staged layout: [h][jt(64)][f(64)][64 j, pair-permuted] bf16
__device__ __align__(16) __nv_bfloat16 g_ftb[H1 * NH * Nn];   // 4 MB
__device__ __align__(16) float g_wt[H1 * NH * NF];            // 1 MB  [h][f][k]
__device__ __align__(16) float2 g_EG1[H1 * Nn];               // (exp(s), exp(.2 s))
__device__ __align__(16) float2 g_FH1[H1 * Nn];               // (exp(nb), exp(.2 nb))
__device__ __align__(16) float g_h[Nn * (H1 * NH)];           // 8 MB
__device__ __align__(16) float g_feats2[Nn * NC];
__device__ __align__(16) float2 g_EG2[Nn];
__device__ __align__(16) float2 g_FH2[Nn];

// ---------------- helpers ----------------
__device__ __forceinline__ uint32_t tf32r(float f) {
    uint32_t r; asm("cvt.rna.tf32.f32 %0, %1;" : "=r"(r) : "f"(f)); return r;
}
__device__ __forceinline__ float tf32f(float f) {
    uint32_t r = tf32r(f); return __uint_as_float(r);
}
__device__ __forceinline__ void mma_tf32(float* c,
                                         uint32_t a0, uint32_t a1, uint32_t a2, uint32_t a3,
                                         uint32_t b0, uint32_t b1) {
    asm volatile(
        "mma.sync.aligned.m16n8k8.row.col.f32.tf32.tf32.f32 "
        "{%0,%1,%2,%3}, {%4,%5,%6,%7}, {%8,%9}, {%0,%1,%2,%3};"
        : "+f"(c[0]), "+f"(c[1]), "+f"(c[2]), "+f"(c[3])
        : "r"(a0), "r"(a1), "r"(a2), "r"(a3), "r"(b0), "r"(b1));
}
__device__ __forceinline__ void mma_bf16(float* c,
                                         uint32_t a0, uint32_t a1, uint32_t a2, uint32_t a3,
                                         uint32_t b0, uint32_t b1) {
    asm volatile(
        "mma.sync.aligned.m16n8k16.row.col.f32.bf16.bf16.f32 "
        "{%0,%1,%2,%3}, {%4,%5,%6,%7}, {%8,%9}, {%0,%1,%2,%3};"
        : "+f"(c[0]), "+f"(c[1]), "+f"(c[2]), "+f"(c[3])
        : "r"(a0), "r"(a1), "r"(a2), "r"(a3), "r"(b0), "r"(b1));
}
__device__ __forceinline__ uint32_t pack_bf16x2(float lo, float hi) {
    uint32_t d;
    asm("cvt.rn.bf16x2.f32 %0, %1, %2;" : "=r"(d) : "f"(hi), "f"(lo));
    return d;
}
__device__ __forceinline__ void cp16(void* dst, const void* src) {
    uint32_t d = (uint32_t)__cvta_generic_to_shared(dst);
    asm volatile("cp.async.cg.shared.global [%0], [%1], 16;" :: "r"(d), "l"(src) : "memory");
}
__device__ __forceinline__ void cp4(void* dst, const void* src) {
    uint32_t d = (uint32_t)__cvta_generic_to_shared(dst);
    asm volatile("cp.async.ca.shared.global [%0], [%1], 4;" :: "r"(d), "l"(src) : "memory");
}
__device__ __forceinline__ void cp_commit() {
    asm volatile("cp.async.commit_group;" ::: "memory");
}
__device__ __forceinline__ void cp_wait_all() {
    asm volatile("cp.async.wait_group 0;" ::: "memory");
}

// ---------------- K1: prep = adjacency bitmask + W1 transpose/round ------------
__global__ void k_prep(const int* __restrict__ adj, const float* __restrict__ W1) {
    __shared__ float t[32][33];
    if (blockIdx.x < 2048) {
        int gw = blockIdx.x * 8 + (threadIdx.x >> 5);
        int lane = threadIdx.x & 31;
        int row = gw >> 2, q = gw & 3;
        const int* base = adj + (size_t)row * Nn + q * 1024;
        unsigned* wbase = g_adj + row * WPR + q * 32;
#pragma unroll 4
        for (int w = 0; w < 32; ++w) {
            unsigned m = __ballot_sync(0xffffffffu, base[w * 32 + lane] > 0);
            if (lane == 0) wbase[w] = m;
        }
    } else {
        int idx = blockIdx.x - 2048;           // 0..255
        int h = idx >> 5;
        int r = idx & 31;
        int kt = (r >> 1) * 32, ft = (r & 1) * 32;
        int x = threadIdx.x & 31, y = threadIdx.x >> 5;
        const float* src = W1 + (size_t)h * NF * NH;
#pragma unroll
        for (int rr = y; rr < 32; rr += 8)
            t[rr][x] = src[(size_t)(kt + rr) * NH + ft + x];
        __syncthreads();
        float* dst = g_wt + (size_t)h * NH * NF;
#pragma unroll
        for (int rr = y; rr < 32; rr += 8)
            dst[(size_t)(ft + rr) * NF + kt + x] = tf32f(t[x][rr]);
    }
}

// ---------------- K2: feats1[h] = x @ W1[h]  tf32 mma + cp.async pipeline ------
__global__ void __launch_bounds__(256, 2) k_gemm1_mma(const float* __restrict__ x) {
    int h = blockIdx.y;
    int i0 = blockIdx.x * 128;
    int tid = threadIdx.x, wid = tid >> 5, lane = tid & 31;
    int gid = lane >> 2, tig = lane & 3;
    __shared__ __align__(16) float Xs[2][128][24];    // 96B rows
    __shared__ __align__(16) float Wt_s[2][64][24];

    int r0 = wid * 16 + gid, r1 = r0 + 8;
    float c[8][4] = {};

    auto stage = [&](int kc, int buf) {
        int a0 = tid, a1 = tid + 256;
        cp16(&Xs[buf][a0 >> 2][(a0 & 3) * 4],
             x + (size_t)(i0 + (a0 >> 2)) * NF + kc * 16 + (a0 & 3) * 4);
        cp16(&Xs[buf][a1 >> 2][(a1 & 3) * 4],
             x + (size_t)(i0 + (a1 >> 2)) * NF + kc * 16 + (a1 & 3) * 4);
        cp16(&Wt_s[buf][tid >> 2][(tid & 3) * 4],
             g_wt + ((size_t)h * NH + (tid >> 2)) * NF + kc * 16 + (tid & 3) * 4);
        cp_commit();
    };

    stage(0, 0);
    for (int kc = 0; kc < NF / 16; ++kc) {
        int buf = kc & 1;
        cp_wait_all();
        __syncthreads();
        if (kc + 1 < NF / 16) stage(kc + 1, buf ^ 1);
#pragma unroll
        for (int ks = 0; ks < 2; ++ks) {
            int k0 = ks * 8 + 2 * tig;
            float2 a02 = *(const float2*)&Xs[buf][r0][k0];
            float2 a13 = *(const float2*)&Xs[buf][r1][k0];
            uint32_t a0 = tf32r(a02.x), a2 = tf32r(a02.y);
            uint32_t a1 = tf32r(a13.x), a3 = tf32r(a13.y);
#pragma unroll
            for (int nt = 0; nt < 8; ++nt) {
                float2 b = *(const float2*)&Wt_s[buf][nt * 8 + gid][k0];
                mma_tf32(c[nt], a0, a1, a2, a3, __float_as_uint(b.x), __float_as_uint(b.y));
            }
        }
    }
    float* o0 = g_feats1 + ((size_t)h * Nn + i0 + r0) * NH;
    float* o1 = g_feats1 + ((size_t)h * Nn + i0 + r1) * NH;
#pragma unroll
    for (int nt = 0; nt < 8; ++nt) {
        int cc = nt * 8 + 2 * tig;
        *(float2*)(o0 + cc) = make_float2(c[nt][0], c[nt][1]);
        *(float2*)(o1 + cc) = make_float2(c[nt][2], c[nt][3]);
    }
}

// ---------------- K3: ftprep = transpose+permute feats1 -> g_ftb, + EG/FH ------
// tile rows are 65 floats (260B, NOT 16B-aligned): smem stores scalar only.
__global__ void __launch_bounds__(256) k_ftprep(const float* __restrict__ as1,
                                                const float* __restrict__ an1) {
    int jt = blockIdx.x, h = blockIdx.y;
    __shared__ float tile[64][65];
    __shared__ float av[64], nv[64];
    int tid = threadIdx.x;
    {
        int r = tid >> 2, fq = (tid & 3) * 16;
        const float* src = g_feats1 + ((size_t)h * Nn + jt * 64 + r) * NH + fq;
#pragma unroll
        for (int v = 0; v < 4; ++v) {
            float4 t = *(const float4*)(src + v * 4);
            tile[r][fq + v * 4 + 0] = t.x;
            tile[r][fq + v * 4 + 1] = t.y;
            tile[r][fq + v * 4 + 2] = t.z;
            tile[r][fq + v * 4 + 3] = t.w;
        }
    }
    if (tid < 64) { av[tid] = as1[h * NH + tid]; nv[tid] = an1[h * NH + tid]; }
    __syncthreads();

    {
        int f = tid >> 2, g = tid & 3;
        uint32_t w[8];
#pragma unroll
        for (int s = 0; s < 8; ++s) {
            int q = (s & 1) ? (s >> 1) + 4 : (s >> 1);
            int j = g * 16 + 2 * q;
            w[s] = pack_bf16x2(tile[j][f], tile[j + 1][f]);
        }
        uint32_t* dst = (uint32_t*)g_ftb + (((size_t)h * 64 + jt) * NH + f) * 32 + g * 8;
        *(uint4*)dst = make_uint4(w[0], w[1], w[2], w[3]);
        *(uint4*)(dst + 4) = make_uint4(w[4], w[5], w[6], w[7]);
    }
    {
        int j = tid >> 2, q4 = (tid & 3) * 16;
        float vs = 0.f, vn = 0.f;
#pragma unroll
        for (int u = 0; u < 16; ++u) {
            float xv = tile[j][q4 + u];
            vs = fmaf(xv, av[q4 + u], vs);
            vn = fmaf(xv, nv[q4 + u], vn);
        }
        vs += __shfl_xor_sync(0xffffffffu, vs, 1);
        vs += __shfl_xor_sync(0xffffffffu, vs, 2);
        vn += __shfl_xor_sync(0xffffffffu, vn, 1);
        vn += __shfl_xor_sync(0xffffffffu, vn, 2);
        if ((tid & 3) == 0) {
            int gi = h * Nn + jt * 64 + j;
            g_EG1[gi] = make_float2(__expf(vs), __expf(0.2f * vs));
            g_FH1[gi] = make_float2(__expf(vn), __expf(0.2f * vn));
        }
    }
}

// ---------------- K4: layer-1 attention, bf16 mma + cp.async pipeline ----------
__global__ void __launch_bounds__(256, 2) k_attn1_mma(const float* __restrict__ b1) {
    int h = blockIdx.y;
    int i0 = blockIdx.x * 128;
    int tid = threadIdx.x, wid = tid >> 5, lane = tid & 31;
    int gid = lane >> 2, tig = lane & 3;

    __shared__ __align__(16) __nv_bfloat16 Ft_s[2][64][80];  // 160B rows
    __shared__ __align__(16) float2 FHs[2][64];
    __shared__ __align__(16) unsigned adjs[2][256];
    __shared__ float Rs[128];

    int r0 = wid * 16 + gid, r1 = r0 + 8;
    float2 eg0 = g_EG1[h * Nn + i0 + r0];
    float2 eg1 = g_EG1[h * Nn + i0 + r1];
    float c[8][4] = {};
    float rs0 = 0.f, rs1 = 0.f;

    const float2* fhsrc = g_FH1 + h * Nn;
    int arow = tid >> 1, ahalf = tid & 1;
    const unsigned* adjsrc = g_adj + (size_t)(i0 + arow) * WPR + ahalf;

    auto stage = [&](int jt, int buf) {
        const char* fbase = (const char*)(g_ftb + ((size_t)(h * 64 + jt) * NH) * 64);
        int c0 = tid, c1 = tid + 256;
        cp16(&Ft_s[buf][c0 >> 3][(c0 & 7) * 8], fbase + c0 * 16);
        cp16(&Ft_s[buf][c1 >> 3][(c1 & 7) * 8], fbase + c1 * 16);
        cp4(&adjs[buf][tid], adjsrc + jt * 2);
        if (tid < 32) cp16(&FHs[buf][tid * 2], fhsrc + jt * 64 + tid * 2);
        cp_commit();
    };

    stage(0, 0);
    for (int jt = 0; jt < Nn / 64; ++jt) {
        int buf = jt & 1;
        cp_wait_all();
        __syncthreads();
        if (jt + 1 < Nn / 64) stage(jt + 1, buf ^ 1);

        unsigned wa0 = adjs[buf][r0 * 2], wb0 = adjs[buf][r0 * 2 + 1];
        unsigned wa1 = adjs[buf][r1 * 2], wb1 = adjs[buf][r1 * 2 + 1];
#pragma unroll
        for (int ks = 0; ks < 4; ++ks) {
            int jb2 = ks * 16;
            unsigned sw0 = ((ks & 2) ? wb0 : wa0) >> ((ks & 1) * 16);
            unsigned sw1 = ((ks & 2) ? wb1 : wa1) >> ((ks & 1) * 16);
            int j0 = 2 * tig, j2 = j0 + 8;
            // contiguous pairs: one float4 = (F_j0,H_j0,F_j0+1,H_j0+1)
            float4 fA = *(const float4*)&FHs[buf][jb2 + j0];
            float4 fB = *(const float4*)&FHs[buf][jb2 + j2];
            float p00 = ((sw0 >> j0) & 1u)       ? fmaxf(eg0.x * fA.x, eg0.y * fA.y) : 0.f;
            float p01 = ((sw0 >> (j0 + 1)) & 1u) ? fmaxf(eg0.x * fA.z, eg0.y * fA.w) : 0.f;
            float p02 = ((sw0 >> j2) & 1u)       ? fmaxf(eg0.x * fB.x, eg0.y * fB.y) : 0.f;
            float p03 = ((sw0 >> (j2 + 1)) & 1u) ? fmaxf(eg0.x * fB.z, eg0.y * fB.w) : 0.f;
            float p10 = ((sw1 >> j0) & 1u)       ? fmaxf(eg1.x * fA.x, eg1.y * fA.y) : 0.f;
            float p11 = ((sw1 >> (j0 + 1)) & 1u) ? fmaxf(eg1.x * fA.z, eg1.y * fA.w) : 0.f;
            float p12 = ((sw1 >> j2) & 1u)       ? fmaxf(eg1.x * fB.x, eg1.y * fB.y) : 0.f;
            float p13 = ((sw1 >> (j2 + 1)) & 1u) ? fmaxf(eg1.x * fB.z, eg1.y * fB.w) : 0.f;
            rs0 += (p00 + p01) + (p02 + p03);
            rs1 += (p10 + p11) + (p12 + p13);
            uint32_t a0 = pack_bf16x2(p00, p01);
            uint32_t a1 = pack_bf16x2(p10, p11);
            uint32_t a2 = pack_bf16x2(p02, p03);
            uint32_t a3 = pack_bf16x2(p12, p13);
#pragma unroll
            for (int nt = 0; nt < 8; ++nt) {
                uint2 bb = *(const uint2*)((const char*)&Ft_s[buf][0][0] +
                                           (nt * 8 + gid) * 160 + ks * 32 + tig * 8);
                mma_bf16(c[nt], a0, a1, a2, a3, bb.x, bb.y);
            }
        }
    }
    rs0 += __shfl_xor_sync(0xffffffffu, rs0, 1);
    rs0 += __shfl_xor_sync(0xffffffffu, rs0, 2);
    rs1 += __shfl_xor_sync(0xffffffffu, rs1, 1);
    rs1 += __shfl_xor_sync(0xffffffffu, rs1, 2);
    if (tig == 0) { Rs[r0] = rs0; Rs[r1] = rs1; }
    __syncthreads();

    float inv0 = 1.0f / Rs[r0];
    float inv1 = 1.0f / Rs[r1];
    const float* bh = b1 + h * NH;
    float* d0 = g_h + (size_t)(i0 + r0) * (H1 * NH) + h * NH;
    float* d1 = g_h + (size_t)(i0 + r1) * (H1 * NH) + h * NH;
#pragma unroll
    for (int nt = 0; nt < 8; ++nt) {
        int cc = nt * 8 + 2 * tig;
        float2 bb = *(const float2*)(bh + cc);
        *(float2*)(d0 + cc) = make_float2(fmaxf(c[nt][0] * inv0 + bb.x, 0.f),
                                          fmaxf(c[nt][1] * inv0 + bb.y, 0.f));
        *(float2*)(d1 + cc) = make_float2(fmaxf(c[nt][2] * inv1 + bb.x, 0.f),
                                          fmaxf(c[nt][3] * inv1 + bb.y, 0.f));
    }
}

// ---------------- K5: feats2 = h @ W2 (K-split x8); factorized exps ------------
__global__ void k_gemm2(const float* __restrict__ W2, const float* __restrict__ as2,
                        const float* __restrict__ an2) {
    __shared__ float Ws[NF * NC];
    int tid = threadIdx.x;
    for (int u = tid; u < NF * NC; u += 256) Ws[u] = W2[u];
    __syncthreads();
    int row = blockIdx.x * 32 + (tid >> 3);
    int sl = tid & 7;
    const float* hr = g_h + (size_t)row * NF + sl * 64;
    float acc[NC] = {};
    for (int k = 0; k < 64; k += 4) {
        float4 xv = *(const float4*)&hr[k];
        const float* wp = &Ws[(sl * 64 + k) * NC];
#pragma unroll
        for (int f = 0; f < NC; ++f) {
            acc[f] = fmaf(xv.x, wp[f], acc[f]);
            acc[f] = fmaf(xv.y, wp[NC + f], acc[f]);
            acc[f] = fmaf(xv.z, wp[2 * NC + f], acc[f]);
            acc[f] = fmaf(xv.w, wp[3 * NC + f], acc[f]);
        }
    }
#pragma unroll
    for (int o = 4; o; o >>= 1)
#pragma unroll
        for (int f = 0; f < NC; ++f)
            acc[f] += __shfl_xor_sync(0xffffffffu, acc[f], o);
    if (sl == 0) {
        float sv = 0.f, nv = 0.f;
#pragma unroll
        for (int f = 0; f < NC; ++f) { sv = fmaf(acc[f], as2[f], sv); nv = fmaf(acc[f], an2[f], nv); }
        float4* fo = (float4*)&g_feats2[(size_t)row * NC];
        fo[0] = make_float4(acc[0], acc[1], acc[2], acc[3]);
        fo[1] = make_float4(acc[4], acc[5], acc[6], acc[7]);
        fo[2] = make_float4(acc[8], acc[9], acc[10], acc[11]);
        fo[3] = make_float4(acc[12], acc[13], acc[14], acc[15]);
        g_EG2[row] = make_float2(__expf(sv), __expf(0.2f * sv));
        g_FH2[row] = make_float2(__expf(nv), __expf(0.2f * nv));
    }
}

// ---------------- K6: layer-2 attention + relu + log_softmax -------------------
// 64 rows per block; each thread: 4 rows x 1 class, Ps read as float4.
__global__ void k_attn2(const float* __restrict__ b2, float* __restrict__ out) {
    int i0 = blockIdx.x * 64;
    int tid = threadIdx.x;
    __shared__ float Ps[64][68];                  // [j][row], 272B rows (16B-mult)
    __shared__ __align__(16) float Fs[64][16];
    __shared__ float2 fhs[64];
    __shared__ float RsP[64][4];
    int pr = tid >> 2, pj = tid & 3;              // P-gen: row pr, 16 j per thread
    int tx = tid & 15, tg = tid >> 4;             // GEMM: class tx, rows tg*4..+3
    float2 eg = g_EG2[i0 + pr];
    const unsigned* bi = g_adj + (size_t)(i0 + pr) * WPR;
    float acc[4] = {0.f, 0.f, 0.f, 0.f};
    float rs = 0.f;

    for (int jt = 0; jt < Nn / 64; ++jt) {
        __syncthreads();
        ((float4*)&Fs[0][0])[tid] = ((const float4*)(g_feats2 + (size_t)jt * 64 * NC))[tid];
        if (tid < 64) fhs[tid] = g_FH2[jt * 64 + tid];
        __syncthreads();
        unsigned w0 = bi[jt * 2], w1 = bi[jt * 2 + 1];
#pragma unroll
        for (int k = 0; k < 16; ++k) {
            int j = pj + k * 4;
            unsigned bit = (j < 32) ? ((w0 >> j) & 1u) : ((w1 >> (j - 32)) & 1u);
            float2 fh = fhs[j];
            float p = bit ? fmaxf(eg.x * fh.x, eg.y * fh.y) : 0.f;
            rs += p;
            Ps[j][pr] = p;
        }
        __syncthreads();
#pragma unroll 8
        for (int j = 0; j < 64; ++j) {
            float4 a = *(const float4*)&Ps[j][tg * 4];
            float b = Fs[j][tx];
            acc[0] = fmaf(a.x, b, acc[0]);
            acc[1] = fmaf(a.y, b, acc[1]);
            acc[2] = fmaf(a.z, b, acc[2]);
            acc[3] = fmaf(a.w, b, acc[3]);
        }
    }
    __syncthreads();
    RsP[pr][pj] = rs;
    __syncthreads();
    float bb = b2[tx];
#pragma unroll
    for (int u = 0; u < 4; ++u) {
        int row = tg * 4 + u;
        float s = RsP[row][0] + RsP[row][1] + RsP[row][2] + RsP[row][3];
        float v = fmaxf(acc[u] / s + bb, 0.f);
        float m = v;
#pragma unroll
        for (int o = 8; o; o >>= 1) m = fmaxf(m, __shfl_xor_sync(0xffffffffu, m, o));
        float e = __expf(v - m);
#pragma unroll
        for (int o = 8; o; o >>= 1) e += __shfl_xor_sync(0xffffffffu, e, o);
        out[(size_t)(i0 + row) * NC + tx] = v - (logf(e) + m);
    }
}

// ---------------- launcher ----------------
extern "C" void kernel_launch(void* const* d_in, const int* in_sizes, int n_in,
                              void* d_out, int out_size) {
    (void)in_sizes; (void)n_in; (void)out_size;
    const float* x   = (const float*)d_in[0];
    const int*   adj = (const int*)d_in[1];
    const float* W1  = (const float*)d_in[2];
    const float* b1  = (const float*)d_in[3];
    const float* as1 = (const float*)d_in[4];
    const float* an1 = (const float*)d_in[5];
    const float* W2  = (const float*)d_in[6];
    const float* b2  = (const float*)d_in[7];
    const float* as2 = (const float*)d_in[8];
    const float* an2 = (const float*)d_in[9];
    float* out = (float*)d_out;

    k_prep<<<2048 + 256, 256>>>(adj, W1);                    // 1
    k_gemm1_mma<<<dim3(Nn / 128, H1), 256>>>(x);             // 2
    k_ftprep<<<dim3(Nn / 64, H1), 256>>>(as1, an1);          // 3
    k_attn1_mma<<<dim3(Nn / 128, H1), 256>>>(b1);            // 4  <- profiled launch
    k_gemm2<<<Nn / 32, 256>>>(W2, as2, an2);                 // 5
    k_attn2<<<Nn / 64, 256>>>(b2, out);                      // 6
}

// round 11
// speedup vs baseline: 1.0693x; 1.0693x over previous
#include <cuda_runtime.h>
#include <cuda_bf16.h>
#include <cstdint>

#define Nn 4096
#define NF 512
#define NH 64
#define H1 8
#define NC 16
#define WPR 128   // words per adjacency row (4096/32)

// ---------------- scratch (static device globals; no allocation) ----------------
__device__ __align__(16) unsigned g_adj[Nn * WPR];            // 2 MB bitmask
__device__ __align__(16) float g_feats1[H1 * Nn * NH];        // 8 MB  [h][i][f]
// g_ftb: MMA-staged layout: [h][jt(64)][f(64)][64 j, pair-permuted] bf16
__device__ __align__(16) __nv_bfloat16 g_ftb[H1 * NH * Nn];   // 4 MB
__device__ __align__(16) float g_wt[H1 * NH * NF];            // 1 MB  [h][f][k]
__device__ __align__(16) float2 g_EG1[H1 * Nn];               // (exp(s), exp(.2 s))
__device__ __align__(16) float2 g_FH1[H1 * Nn];               // (exp(nb), exp(.2 nb))
__device__ __align__(16) float g_h[Nn * (H1 * NH)];           // 8 MB
__device__ __align__(16) float g_feats2[Nn * NC];
__device__ __align__(16) float2 g_EG2[Nn];
__device__ __align__(16) float2 g_FH2[Nn];

// ---------------- helpers ----------------
__device__ __forceinline__ uint32_t tf32r(float f) {
    uint32_t r; asm("cvt.rna.tf32.f32 %0, %1;" : "=r"(r) : "f"(f)); return r;
}
__device__ __forceinline__ float tf32f(float f) {
    uint32_t r = tf32r(f); return __uint_as_float(r);
}
__device__ __forceinline__ void mma_tf32(float* c,
                                         uint32_t a0, uint32_t a1, uint32_t a2, uint32_t a3,
                                         uint32_t b0, uint32_t b1) {
    asm volatile(
        "mma.sync.aligned.m16n8k8.row.col.f32.tf32.tf32.f32 "
        "{%0,%1,%2,%3}, {%4,%5,%6,%7}, {%8,%9}, {%0,%1,%2,%3};"
        : "+f"(c[0]), "+f"(c[1]), "+f"(c[2]), "+f"(c[3])
        : "r"(a0), "r"(a1), "r"(a2), "r"(a3), "r"(b0), "r"(b1));
}
__device__ __forceinline__ void mma_bf16(float* c,
                                         uint32_t a0, uint32_t a1, uint32_t a2, uint32_t a3,
                                         uint32_t b0, uint32_t b1) {
    asm volatile(
        "mma.sync.aligned.m16n8k16.row.col.f32.bf16.bf16.f32 "
        "{%0,%1,%2,%3}, {%4,%5,%6,%7}, {%8,%9}, {%0,%1,%2,%3};"
        : "+f"(c[0]), "+f"(c[1]), "+f"(c[2]), "+f"(c[3])
        : "r"(a0), "r"(a1), "r"(a2), "r"(a3), "r"(b0), "r"(b1));
}
__device__ __forceinline__ uint32_t pack_bf16x2(float lo, float hi) {
    uint32_t d;
    asm("cvt.rn.bf16x2.f32 %0, %1, %2;" : "=r"(d) : "f"(hi), "f"(lo));
    return d;
}
__device__ __forceinline__ void cp16(void* dst, const void* src) {
    uint32_t d = (uint32_t)__cvta_generic_to_shared(dst);
    asm volatile("cp.async.cg.shared.global [%0], [%1], 16;" :: "r"(d), "l"(src) : "memory");
}
__device__ __forceinline__ void cp4(void* dst, const void* src) {
    uint32_t d = (uint32_t)__cvta_generic_to_shared(dst);
    asm volatile("cp.async.ca.shared.global [%0], [%1], 4;" :: "r"(d), "l"(src) : "memory");
}
__device__ __forceinline__ void cp_commit() {
    asm volatile("cp.async.commit_group;" ::: "memory");
}
__device__ __forceinline__ void cp_wait_all() {
    asm volatile("cp.async.wait_group 0;" ::: "memory");
}
// bf16x2 AND-mask from 2 adjacent adjacency bits in t (bit0 -> low half, bit1 -> high)
__device__ __forceinline__ uint32_t bitmask2(unsigned t) {
    return (t & 1u) * 0xFFFFu + (t & 2u) * 0x7FFF8000u;
}

// ---------------- K1: prep = adjacency bitmask + W1 transpose/round ------------
__global__ void k_prep(const int* __restrict__ adj, const float* __restrict__ W1) {
    __shared__ float t[32][33];
    if (blockIdx.x < 2048) {
        int gw = blockIdx.x * 8 + (threadIdx.x >> 5);
        int lane = threadIdx.x & 31;
        int row = gw >> 2, q = gw & 3;
        const int* base = adj + (size_t)row * Nn + q * 1024;
        unsigned* wbase = g_adj + row * WPR + q * 32;
#pragma unroll 4
        for (int w = 0; w < 32; ++w) {
            unsigned m = __ballot_sync(0xffffffffu, base[w * 32 + lane] > 0);
            if (lane == 0) wbase[w] = m;
        }
    } else {
        int idx = blockIdx.x - 2048;           // 0..255
        int h = idx >> 5;
        int r = idx & 31;
        int kt = (r >> 1) * 32, ft = (r & 1) * 32;
        int x = threadIdx.x & 31, y = threadIdx.x >> 5;
        const float* src = W1 + (size_t)h * NF * NH;
#pragma unroll
        for (int rr = y; rr < 32; rr += 8)
            t[rr][x] = src[(size_t)(kt + rr) * NH + ft + x];
        __syncthreads();
        float* dst = g_wt + (size_t)h * NH * NF;
#pragma unroll
        for (int rr = y; rr < 32; rr += 8)
            dst[(size_t)(ft + rr) * NF + kt + x] = tf32f(t[x][rr]);
    }
}

// ---------------- K2: feats1[h] = x @ W1[h]  via mma.sync tf32 (round-9) -------
__global__ void __launch_bounds__(256, 2) k_gemm1_mma(const float* __restrict__ x) {
    int h = blockIdx.y;
    int i0 = blockIdx.x * 128;
    int tid = threadIdx.x, wid = tid >> 5, lane = tid & 31;
    int gid = lane >> 2, tig = lane & 3;
    __shared__ float Xs[128][40];    // 160B rows: float4-safe
    __shared__ float Wt_s[64][40];

    int r0 = wid * 16 + gid, r1 = r0 + 8;
    float c[8][4] = {};

    int srow = tid >> 1, shalf = tid & 1;
    int sf = tid >> 2, sq = tid & 3;
    const float* xsrc = x + (size_t)(i0 + srow) * NF + shalf * 16;
    const float* wsrc = g_wt + ((size_t)h * NH + sf) * NF + sq * 8;

    for (int kc = 0; kc < NF / 32; ++kc) {
        __syncthreads();
#pragma unroll
        for (int v = 0; v < 4; ++v) {
            float4 t = *(const float4*)(xsrc + kc * 32 + v * 4);
            t.x = tf32f(t.x); t.y = tf32f(t.y); t.z = tf32f(t.z); t.w = tf32f(t.w);
            *(float4*)&Xs[srow][shalf * 16 + v * 4] = t;
        }
        {
            float4 v0 = *(const float4*)(wsrc + kc * 32);
            float4 v1 = *(const float4*)(wsrc + kc * 32 + 4);
            *(float4*)&Wt_s[sf][sq * 8] = v0;
            *(float4*)&Wt_s[sf][sq * 8 + 4] = v1;
        }
        __syncthreads();
#pragma unroll
        for (int ks = 0; ks < 4; ++ks) {
            int k0 = ks * 8 + 2 * tig;
            float2 a02 = *(const float2*)&Xs[r0][k0];
            float2 a13 = *(const float2*)&Xs[r1][k0];
            uint32_t a0 = __float_as_uint(a02.x), a2 = __float_as_uint(a02.y);
            uint32_t a1 = __float_as_uint(a13.x), a3 = __float_as_uint(a13.y);
#pragma unroll
            for (int nt = 0; nt < 8; ++nt) {
                float2 b = *(const float2*)&Wt_s[nt * 8 + gid][k0];
                mma_tf32(c[nt], a0, a1, a2, a3, __float_as_uint(b.x), __float_as_uint(b.y));
            }
        }
    }
    float* o0 = g_feats1 + ((size_t)h * Nn + i0 + r0) * NH;
    float* o1 = g_feats1 + ((size_t)h * Nn + i0 + r1) * NH;
#pragma unroll
    for (int nt = 0; nt < 8; ++nt) {
        int cc = nt * 8 + 2 * tig;
        *(float2*)(o0 + cc) = make_float2(c[nt][0], c[nt][1]);
        *(float2*)(o1 + cc) = make_float2(c[nt][2], c[nt][3]);
    }
}

// ---------------- K3: ftprep = transpose+permute feats1 -> g_ftb, + EG/FH ------
// tile rows are 65 floats (260B, NOT 16B-aligned): smem stores scalar only.
__global__ void __launch_bounds__(256) k_ftprep(const float* __restrict__ as1,
                                                const float* __restrict__ an1) {
    int jt = blockIdx.x, h = blockIdx.y;
    __shared__ float tile[64][65];
    __shared__ float av[64], nv[64];
    int tid = threadIdx.x;
    {
        int r = tid >> 2, fq = (tid & 3) * 16;
        const float* src = g_feats1 + ((size_t)h * Nn + jt * 64 + r) * NH + fq;
#pragma unroll
        for (int v = 0; v < 4; ++v) {
            float4 t = *(const float4*)(src + v * 4);
            tile[r][fq + v * 4 + 0] = t.x;
            tile[r][fq + v * 4 + 1] = t.y;
            tile[r][fq + v * 4 + 2] = t.z;
            tile[r][fq + v * 4 + 3] = t.w;
        }
    }
    if (tid < 64) { av[tid] = as1[h * NH + tid]; nv[tid] = an1[h * NH + tid]; }
    __syncthreads();

    {
        int f = tid >> 2, g = tid & 3;
        uint32_t w[8];
#pragma unroll
        for (int s = 0; s < 8; ++s) {
            int q = (s & 1) ? (s >> 1) + 4 : (s >> 1);
            int j = g * 16 + 2 * q;
            w[s] = pack_bf16x2(tile[j][f], tile[j + 1][f]);
        }
        uint32_t* dst = (uint32_t*)g_ftb + (((size_t)h * 64 + jt) * NH + f) * 32 + g * 8;
        *(uint4*)dst = make_uint4(w[0], w[1], w[2], w[3]);
        *(uint4*)(dst + 4) = make_uint4(w[4], w[5], w[6], w[7]);
    }
    {
        int j = tid >> 2, q4 = (tid & 3) * 16;
        float vs = 0.f, vn = 0.f;
#pragma unroll
        for (int u = 0; u < 16; ++u) {
            float xv = tile[j][q4 + u];
            vs = fmaf(xv, av[q4 + u], vs);
            vn = fmaf(xv, nv[q4 + u], vn);
        }
        vs += __shfl_xor_sync(0xffffffffu, vs, 1);
        vs += __shfl_xor_sync(0xffffffffu, vs, 2);
        vn += __shfl_xor_sync(0xffffffffu, vn, 1);
        vn += __shfl_xor_sync(0xffffffffu, vn, 2);
        if ((tid & 3) == 0) {
            int gi = h * Nn + jt * 64 + j;
            g_EG1[gi] = make_float2(__expf(vs), __expf(0.2f * vs));
            g_FH1[gi] = make_float2(__expf(vn), __expf(0.2f * vn));
        }
    }
}

// ---------------- K4: layer-1 attention, bf16 mma + cp.async pipeline ----------
// New: unconditional P + LOP-AND masking; row-sums via 9th N-tile (ones column).
__global__ void __launch_bounds__(256, 2) k_attn1_mma(const float* __restrict__ b1) {
    int h = blockIdx.y;
    int i0 = blockIdx.x * 128;
    int tid = threadIdx.x, wid = tid >> 5, lane = tid & 31;
    int gid = lane >> 2, tig = lane & 3;

    __shared__ __align__(16) __nv_bfloat16 Ft_s[2][72][80];  // rows 64..71: rowsum tile
    __shared__ __align__(16) float2 FHs[2][64];
    __shared__ __align__(16) unsigned adjs[2][256];
    __shared__ float Rs[128];

    int r0 = wid * 16 + gid, r1 = r0 + 8;
    float2 eg0 = g_EG1[h * Nn + i0 + r0];
    float2 eg1 = g_EG1[h * Nn + i0 + r1];
    float c[9][4] = {};

    const float2* fhsrc = g_FH1 + h * Nn;
    int arow = tid >> 1, ahalf = tid & 1;
    const unsigned* adjsrc = g_adj + (size_t)(i0 + arow) * WPR + ahalf;

    // init rowsum tile: row 64 = bf16 ones, rows 65..71 = zeros (both buffers)
    for (int u = tid; u < 2 * 8 * 40; u += 256) {
        int buf = u / 320, rem = u % 320;
        int row = 64 + rem / 40, col = rem % 40;
        ((uint32_t*)&Ft_s[buf][row][0])[col] = (row == 64) ? 0x3F803F80u : 0u;
    }

    auto stage = [&](int jt, int buf) {
        const char* fbase = (const char*)(g_ftb + ((size_t)(h * 64 + jt) * NH) * 64);
        int c0 = tid, c1 = tid + 256;
        cp16(&Ft_s[buf][c0 >> 3][(c0 & 7) * 8], fbase + c0 * 16);
        cp16(&Ft_s[buf][c1 >> 3][(c1 & 7) * 8], fbase + c1 * 16);
        cp4(&adjs[buf][tid], adjsrc + jt * 2);
        if (tid < 32) cp16(&FHs[buf][tid * 2], fhsrc + jt * 64 + tid * 2);
        cp_commit();
    };

    stage(0, 0);
    for (int jt = 0; jt < Nn / 64; ++jt) {
        int buf = jt & 1;
        cp_wait_all();
        __syncthreads();
        if (jt + 1 < Nn / 64) stage(jt + 1, buf ^ 1);

        unsigned wa0 = adjs[buf][r0 * 2], wb0 = adjs[buf][r0 * 2 + 1];
        unsigned wa1 = adjs[buf][r1 * 2], wb1 = adjs[buf][r1 * 2 + 1];
#pragma unroll
        for (int ks = 0; ks < 4; ++ks) {
            int jb2 = ks * 16;
            unsigned sw0 = ((ks & 2) ? wb0 : wa0) >> ((ks & 1) * 16);
            unsigned sw1 = ((ks & 2) ? wb1 : wa1) >> ((ks & 1) * 16);
            int j0 = 2 * tig, j2 = j0 + 8;
            float4 fA = *(const float4*)&FHs[buf][jb2 + j0];  // F0,H0,F1,H1
            float4 fB = *(const float4*)&FHs[buf][jb2 + j2];
            // unconditional P (finite; masked later by AND)
            float p00 = fmaxf(eg0.x * fA.x, eg0.y * fA.y);
            float p01 = fmaxf(eg0.x * fA.z, eg0.y * fA.w);
            float p02 = fmaxf(eg0.x * fB.x, eg0.y * fB.y);
            float p03 = fmaxf(eg0.x * fB.z, eg0.y * fB.w);
            float p10 = fmaxf(eg1.x * fA.x, eg1.y * fA.y);
            float p11 = fmaxf(eg1.x * fA.z, eg1.y * fA.w);
            float p12 = fmaxf(eg1.x * fB.x, eg1.y * fB.y);
            float p13 = fmaxf(eg1.x * fB.z, eg1.y * fB.w);
            unsigned t0 = sw0 >> j0, t1 = sw1 >> j0;
            unsigned t2 = sw0 >> j2, t3 = sw1 >> j2;
            uint32_t a0 = pack_bf16x2(p00, p01) & bitmask2(t0);
            uint32_t a1 = pack_bf16x2(p10, p11) & bitmask2(t1);
            uint32_t a2 = pack_bf16x2(p02, p03) & bitmask2(t2);
            uint32_t a3 = pack_bf16x2(p12, p13) & bitmask2(t3);
#pragma unroll
            for (int nt = 0; nt < 9; ++nt) {
                uint2 bb = *(const uint2*)((const char*)&Ft_s[buf][0][0] +
                                           (nt * 8 + gid) * 160 + ks * 32 + tig * 8);
                mma_bf16(c[nt], a0, a1, a2, a3, bb.x, bb.y);
            }
        }
    }
    // rowsum lives in D column 64 -> c[8][0] (r0) / c[8][2] (r1) on tig==0 lanes
    if (tig == 0) { Rs[r0] = c[8][0]; Rs[r1] = c[8][2]; }
    __syncthreads();

    float inv0 = 1.0f / Rs[r0];
    float inv1 = 1.0f / Rs[r1];
    const float* bh = b1 + h * NH;
    float* d0 = g_h + (size_t)(i0 + r0) * (H1 * NH) + h * NH;
    float* d1 = g_h + (size_t)(i0 + r1) * (H1 * NH) + h * NH;
#pragma unroll
    for (int nt = 0; nt < 8; ++nt) {
        int cc = nt * 8 + 2 * tig;
        float2 bb = *(const float2*)(bh + cc);
        *(float2*)(d0 + cc) = make_float2(fmaxf(c[nt][0] * inv0 + bb.x, 0.f),
                                          fmaxf(c[nt][1] * inv0 + bb.y, 0.f));
        *(float2*)(d1 + cc) = make_float2(fmaxf(c[nt][2] * inv1 + bb.x, 0.f),
                                          fmaxf(c[nt][3] * inv1 + bb.y, 0.f));
    }
}

// ---------------- K5: feats2 = h @ W2 (K-split x8); factorized exps ------------
__global__ void k_gemm2(const float* __restrict__ W2, const float* __restrict__ as2,
                        const float* __restrict__ an2) {
    __shared__ float Ws[NF * NC];
    int tid = threadIdx.x;
    for (int u = tid; u < NF * NC; u += 256) Ws[u] = W2[u];
    __syncthreads();
    int row = blockIdx.x * 32 + (tid >> 3);
    int sl = tid & 7;
    const float* hr = g_h + (size_t)row * NF + sl * 64;
    float acc[NC] = {};
    for (int k = 0; k < 64; k += 4) {
        float4 xv = *(const float4*)&hr[k];
        const float* wp = &Ws[(sl * 64 + k) * NC];
#pragma unroll
        for (int f = 0; f < NC; ++f) {
            acc[f] = fmaf(xv.x, wp[f], acc[f]);
            acc[f] = fmaf(xv.y, wp[NC + f], acc[f]);
            acc[f] = fmaf(xv.z, wp[2 * NC + f], acc[f]);
            acc[f] = fmaf(xv.w, wp[3 * NC + f], acc[f]);
        }
    }
#pragma unroll
    for (int o = 4; o; o >>= 1)
#pragma unroll
        for (int f = 0; f < NC; ++f)
            acc[f] += __shfl_xor_sync(0xffffffffu, acc[f], o);
    if (sl == 0) {
        float sv = 0.f, nv = 0.f;
#pragma unroll
        for (int f = 0; f < NC; ++f) { sv = fmaf(acc[f], as2[f], sv); nv = fmaf(acc[f], an2[f], nv); }
        float4* fo = (float4*)&g_feats2[(size_t)row * NC];
        fo[0] = make_float4(acc[0], acc[1], acc[2], acc[3]);
        fo[1] = make_float4(acc[4], acc[5], acc[6], acc[7]);
        fo[2] = make_float4(acc[8], acc[9], acc[10], acc[11]);
        fo[3] = make_float4(acc[12], acc[13], acc[14], acc[15]);
        g_EG2[row] = make_float2(__expf(sv), __expf(0.2f * sv));
        g_FH2[row] = make_float2(__expf(nv), __expf(0.2f * nv));
    }
}

// ---------------- K6: layer-2 attention + relu + log_softmax (round-9) ---------
__global__ void k_attn2(const float* __restrict__ b2, float* __restrict__ out) {
    int i0 = blockIdx.x * 32;
    int tid = threadIdx.x;
    __shared__ float Ps[64][36];
    __shared__ __align__(16) float Fs[64][16];
    __shared__ float2 fhs[64];
    __shared__ float RsP[32][8];
    int pr = tid >> 3, pj = tid & 7;
    int irow = i0 + pr;
    float2 eg = g_EG2[irow];
    const unsigned* bi = g_adj + (size_t)irow * WPR;
    int tx = tid & 15, tq = tid >> 4;
    float acc0 = 0.f, acc1 = 0.f, rs = 0.f;

    for (int jt = 0; jt < Nn / 64; ++jt) {
        __syncthreads();
        ((float4*)&Fs[0][0])[tid] = ((const float4*)(g_feats2 + (size_t)jt * 64 * NC))[tid];
        if (tid < 64) fhs[tid] = g_FH2[jt * 64 + tid];
        __syncthreads();
        unsigned w0 = bi[jt * 2], w1 = bi[jt * 2 + 1];
#pragma unroll
        for (int k = 0; k < 8; ++k) {
            int j = pj + k * 8;
            unsigned bit = (j < 32) ? ((w0 >> j) & 1u) : ((w1 >> (j - 32)) & 1u);
            float2 fh = fhs[j];
            float p = bit ? fmaxf(eg.x * fh.x, eg.y * fh.y) : 0.f;
            rs += p;
            Ps[j][pr] = p;
        }
        __syncthreads();
#pragma unroll 8
        for (int j = 0; j < 64; ++j) {
            float b = Fs[j][tx];
            acc0 = fmaf(Ps[j][tq * 2], b, acc0);
            acc1 = fmaf(Ps[j][tq * 2 + 1], b, acc1);
        }
    }
    __syncthreads();
    RsP[pr][pj] = rs;
    __syncthreads();
    float s0 = 0.f, s1 = 0.f;
#pragma unroll
    for (int k = 0; k < 8; ++k) { s0 += RsP[tq * 2][k]; s1 += RsP[tq * 2 + 1][k]; }
    float bb = b2[tx];
    float v0 = fmaxf(acc0 / s0 + bb, 0.f);
    float v1 = fmaxf(acc1 / s1 + bb, 0.f);
    float m0 = v0, m1 = v1;
#pragma unroll
    for (int o = 8; o; o >>= 1) {
        m0 = fmaxf(m0, __shfl_xor_sync(0xffffffffu, m0, o));
        m1 = fmaxf(m1, __shfl_xor_sync(0xffffffffu, m1, o));
    }
    float e0 = __expf(v0 - m0), e1 = __expf(v1 - m1);
#pragma unroll
    for (int o = 8; o; o >>= 1) {
        e0 += __shfl_xor_sync(0xffffffffu, e0, o);
        e1 += __shfl_xor_sync(0xffffffffu, e1, o);
    }
    out[(size_t)(i0 + tq * 2 + 0) * NC + tx] = v0 - (logf(e0) + m0);
    out[(size_t)(i0 + tq * 2 + 1) * NC + tx] = v1 - (logf(e1) + m1);
}

// ---------------- launcher ----------------
extern "C" void kernel_launch(void* const* d_in, const int* in_sizes, int n_in,
                              void* d_out, int out_size) {
    (void)in_sizes; (void)n_in; (void)out_size;
    const float* x   = (const float*)d_in[0];
    const int*   adj = (const int*)d_in[1];
    const float* W1  = (const float*)d_in[2];
    const float* b1  = (const float*)d_in[3];
    const float* as1 = (const float*)d_in[4];
    const float* an1 = (const float*)d_in[5];
    const float* W2  = (const float*)d_in[6];
    const float* b2  = (const float*)d_in[7];
    const float* as2 = (const float*)d_in[8];
    const float* an2 = (const float*)d_in[9];
    float* out = (float*)d_out;

    k_prep<<<2048 + 256, 256>>>(adj, W1);                    // 1
    k_gemm1_mma<<<dim3(Nn / 128, H1), 256>>>(x);             // 2
    k_ftprep<<<dim3(Nn / 64, H1), 256>>>(as1, an1);          // 3
    k_attn1_mma<<<dim3(Nn / 128, H1), 256>>>(b1);            // 4  <- profiled launch
    k_gemm2<<<Nn / 32, 256>>>(W2, as2, an2);                 // 5
    k_attn2<<<Nn / 32, 256>>>(b2, out);                      // 6
}

// round 12
// speedup vs baseline: 1.1391x; 1.0653x over previous
#include <cuda_runtime.h>
#include <cuda_bf16.h>
#include <cstdint>

#define Nn 4096
#define NF 512
#define NH 64
#define H1 8
#define NC 16
#define WPR 128   // words per adjacency row (4096/32)

// ---------------- scratch (static device globals; no allocation) ----------------
__device__ __align__(16) unsigned g_adj[Nn * WPR];            // 2 MB bitmask
// g_ftb: MMA-staged layout: [h][jt(64)][f(64)][64 j, pair-permuted] bf16
__device__ __align__(16) __nv_bfloat16 g_ftb[H1 * NH * Nn];   // 4 MB
__device__ __align__(16) float g_wt[H1 * NH * NF];            // 1 MB  [h][f][k]
__device__ __align__(16) float2 g_EG1[H1 * Nn];               // (exp(s), exp(.2 s))
__device__ __align__(16) float2 g_FH1[H1 * Nn];               // (exp(nb), exp(.2 nb))
__device__ __align__(16) float g_h[Nn * (H1 * NH)];           // 8 MB
__device__ __align__(16) float g_feats2[Nn * NC];
__device__ __align__(16) float2 g_EG2[Nn];
__device__ __align__(16) float2 g_FH2[Nn];

// ---------------- helpers ----------------
__device__ __forceinline__ uint32_t tf32r(float f) {
    uint32_t r; asm("cvt.rna.tf32.f32 %0, %1;" : "=r"(r) : "f"(f)); return r;
}
__device__ __forceinline__ float tf32f(float f) {
    uint32_t r = tf32r(f); return __uint_as_float(r);
}
__device__ __forceinline__ void mma_tf32(float* c,
                                         uint32_t a0, uint32_t a1, uint32_t a2, uint32_t a3,
                                         uint32_t b0, uint32_t b1) {
    asm volatile(
        "mma.sync.aligned.m16n8k8.row.col.f32.tf32.tf32.f32 "
        "{%0,%1,%2,%3}, {%4,%5,%6,%7}, {%8,%9}, {%0,%1,%2,%3};"
        : "+f"(c[0]), "+f"(c[1]), "+f"(c[2]), "+f"(c[3])
        : "r"(a0), "r"(a1), "r"(a2), "r"(a3), "r"(b0), "r"(b1));
}
__device__ __forceinline__ void mma_bf16(float* c,
                                         uint32_t a0, uint32_t a1, uint32_t a2, uint32_t a3,
                                         uint32_t b0, uint32_t b1) {
    asm volatile(
        "mma.sync.aligned.m16n8k16.row.col.f32.bf16.bf16.f32 "
        "{%0,%1,%2,%3}, {%4,%5,%6,%7}, {%8,%9}, {%0,%1,%2,%3};"
        : "+f"(c[0]), "+f"(c[1]), "+f"(c[2]), "+f"(c[3])
        : "r"(a0), "r"(a1), "r"(a2), "r"(a3), "r"(b0), "r"(b1));
}
__device__ __forceinline__ uint32_t pack_bf16x2(float lo, float hi) {
    uint32_t d;
    asm("cvt.rn.bf16x2.f32 %0, %1, %2;" : "=r"(d) : "f"(hi), "f"(lo));
    return d;
}
__device__ __forceinline__ void cp16(void* dst, const void* src) {
    uint32_t d = (uint32_t)__cvta_generic_to_shared(dst);
    asm volatile("cp.async.cg.shared.global [%0], [%1], 16;" :: "r"(d), "l"(src) : "memory");
}
__device__ __forceinline__ void cp_commit() {
    asm volatile("cp.async.commit_group;" ::: "memory");
}
__device__ __forceinline__ void cp_wait_all() {
    asm volatile("cp.async.wait_group 0;" ::: "memory");
}
// bf16x2 AND-mask from 2 adjacent adjacency bits in t (bit0 -> low half, bit1 -> high)
__device__ __forceinline__ uint32_t bitmask2(unsigned t) {
    return (t & 1u) * 0xFFFFu + (t & 2u) * 0x7FFF8000u;
}

// ---------------- K1: prep = adjacency bitmask + W1 transpose/round ------------
__global__ void k_prep(const int* __restrict__ adj, const float* __restrict__ W1) {
    __shared__ float t[32][33];
    if (blockIdx.x < 2048) {
        int gw = blockIdx.x * 8 + (threadIdx.x >> 5);
        int lane = threadIdx.x & 31;
        int row = gw >> 2, q = gw & 3;
        const int* base = adj + (size_t)row * Nn + q * 1024;
        unsigned* wbase = g_adj + row * WPR + q * 32;
#pragma unroll 4
        for (int w = 0; w < 32; ++w) {
            unsigned m = __ballot_sync(0xffffffffu, base[w * 32 + lane] > 0);
            if (lane == 0) wbase[w] = m;
        }
    } else {
        int idx = blockIdx.x - 2048;           // 0..255
        int h = idx >> 5;
        int r = idx & 31;
        int kt = (r >> 1) * 32, ft = (r & 1) * 32;
        int x = threadIdx.x & 31, y = threadIdx.x >> 5;
        const float* src = W1 + (size_t)h * NF * NH;
#pragma unroll
        for (int rr = y; rr < 32; rr += 8)
            t[rr][x] = src[(size_t)(kt + rr) * NH + ft + x];
        __syncthreads();
        float* dst = g_wt + (size_t)h * NH * NF;
#pragma unroll
        for (int rr = y; rr < 32; rr += 8)
            dst[(size_t)(ft + rr) * NF + kt + x] = tf32f(t[x][rr]);
    }
}

// ---------------- K2: gemm1 + fused ftb-permute + EG/FH epilogue ---------------
// feats1 = x @ W1[h] (tf32 mma), written directly as permuted bf16 g_ftb;
// EG1/FH1 computed from accumulators (no g_feats1 intermediate).
__global__ void __launch_bounds__(256, 2) k_gemm1_mma(const float* __restrict__ x,
                                                      const float* __restrict__ as1,
                                                      const float* __restrict__ an1) {
    int h = blockIdx.y;
    int i0 = blockIdx.x * 128;
    int tid = threadIdx.x, wid = tid >> 5, lane = tid & 31;
    int gid = lane >> 2, tig = lane & 3;
    __shared__ float Xs[128][40];    // 160B rows
    __shared__ float Wt_s[64][40];
    __shared__ __align__(16) float avs[64], nvs[64];

    if (tid < 64) { avs[tid] = as1[h * NH + tid]; nvs[tid] = an1[h * NH + tid]; }

    int r0 = wid * 16 + gid, r1 = r0 + 8;
    float c[8][4] = {};

    int srow = tid >> 1, shalf = tid & 1;
    int sf = tid >> 2, sq = tid & 3;
    const float* xsrc = x + (size_t)(i0 + srow) * NF + shalf * 16;
    const float* wsrc = g_wt + ((size_t)h * NH + sf) * NF + sq * 8;

    for (int kc = 0; kc < NF / 32; ++kc) {
        __syncthreads();
#pragma unroll
        for (int v = 0; v < 4; ++v) {
            float4 t = *(const float4*)(xsrc + kc * 32 + v * 4);
            t.x = tf32f(t.x); t.y = tf32f(t.y); t.z = tf32f(t.z); t.w = tf32f(t.w);
            *(float4*)&Xs[srow][shalf * 16 + v * 4] = t;
        }
        {
            float4 v0 = *(const float4*)(wsrc + kc * 32);
            float4 v1 = *(const float4*)(wsrc + kc * 32 + 4);
            *(float4*)&Wt_s[sf][sq * 8] = v0;
            *(float4*)&Wt_s[sf][sq * 8 + 4] = v1;
        }
        __syncthreads();
#pragma unroll
        for (int ks = 0; ks < 4; ++ks) {
            int k0 = ks * 8 + 2 * tig;
            float2 a02 = *(const float2*)&Xs[r0][k0];
            float2 a13 = *(const float2*)&Xs[r1][k0];
            uint32_t a0 = __float_as_uint(a02.x), a2 = __float_as_uint(a02.y);
            uint32_t a1 = __float_as_uint(a13.x), a3 = __float_as_uint(a13.y);
#pragma unroll
            for (int nt = 0; nt < 8; ++nt) {
                float2 b = *(const float2*)&Wt_s[nt * 8 + gid][k0];
                mma_tf32(c[nt], a0, a1, a2, a3, __float_as_uint(b.x), __float_as_uint(b.y));
            }
        }
    }

    // ---- fused epilogue 1: permuted bf16 g_ftb via shuffle pairing ----
    // rows r0/r1 pair with rows r0+1/r1+1 held by lane+4 (gid+1).
    int jt = (i0 >> 6) + (wid >> 2);           // global 64-row tile
    int jl0 = r0 & 63, jl1 = r1 & 63;
    int q0 = (jl0 & 15) >> 1, q1 = (jl1 & 15) >> 1;
    int w0o = (jl0 >> 4) * 8 + (q0 < 4 ? 2 * q0 : 2 * (q0 - 4) + 1);
    int w1o = (jl1 >> 4) * 8 + (q1 < 4 ? 2 * q1 : 2 * (q1 - 4) + 1);
    uint32_t* tbase = (uint32_t*)g_ftb + ((size_t)(h * 64 + jt) * 64) * 32;
    bool evengid = ((gid & 1) == 0);
#pragma unroll
    for (int nt = 0; nt < 8; ++nt) {
        float u0 = __shfl_down_sync(0xffffffffu, c[nt][0], 4);
        float u1 = __shfl_down_sync(0xffffffffu, c[nt][1], 4);
        float u2 = __shfl_down_sync(0xffffffffu, c[nt][2], 4);
        float u3 = __shfl_down_sync(0xffffffffu, c[nt][3], 4);
        if (evengid) {
            int f0 = nt * 8 + 2 * tig;
            tbase[(f0 + 0) * 32 + w0o] = pack_bf16x2(c[nt][0], u0);
            tbase[(f0 + 1) * 32 + w0o] = pack_bf16x2(c[nt][1], u1);
            tbase[(f0 + 0) * 32 + w1o] = pack_bf16x2(c[nt][2], u2);
            tbase[(f0 + 1) * 32 + w1o] = pack_bf16x2(c[nt][3], u3);
        }
    }
    // ---- fused epilogue 2: EG/FH per row ----
    float vs0 = 0.f, vn0 = 0.f, vs1 = 0.f, vn1 = 0.f;
#pragma unroll
    for (int nt = 0; nt < 8; ++nt) {
        int f0 = nt * 8 + 2 * tig;
        float2 av = *(const float2*)&avs[f0];
        float2 nv = *(const float2*)&nvs[f0];
        vs0 += c[nt][0] * av.x + c[nt][1] * av.y;
        vs1 += c[nt][2] * av.x + c[nt][3] * av.y;
        vn0 += c[nt][0] * nv.x + c[nt][1] * nv.y;
        vn1 += c[nt][2] * nv.x + c[nt][3] * nv.y;
    }
    vs0 += __shfl_xor_sync(0xffffffffu, vs0, 1); vs0 += __shfl_xor_sync(0xffffffffu, vs0, 2);
    vs1 += __shfl_xor_sync(0xffffffffu, vs1, 1); vs1 += __shfl_xor_sync(0xffffffffu, vs1, 2);
    vn0 += __shfl_xor_sync(0xffffffffu, vn0, 1); vn0 += __shfl_xor_sync(0xffffffffu, vn0, 2);
    vn1 += __shfl_xor_sync(0xffffffffu, vn1, 1); vn1 += __shfl_xor_sync(0xffffffffu, vn1, 2);
    if (tig == 0) {
        int gi0 = h * Nn + i0 + r0, gi1 = h * Nn + i0 + r1;
        g_EG1[gi0] = make_float2(__expf(vs0), __expf(0.2f * vs0));
        g_FH1[gi0] = make_float2(__expf(vn0), __expf(0.2f * vn0));
        g_EG1[gi1] = make_float2(__expf(vs1), __expf(0.2f * vs1));
        g_FH1[gi1] = make_float2(__expf(vn1), __expf(0.2f * vn1));
    }
}

// ---------------- K3: layer-1 attention, bf16 mma, 128-j chunks ----------------
// rowsum via constant B-fragment (ones column n=64): zero extra LDS/smem.
__global__ void __launch_bounds__(256, 2) k_attn1_mma(const float* __restrict__ b1) {
    int h = blockIdx.y;
    int i0 = blockIdx.x * 128;
    int tid = threadIdx.x, wid = tid >> 5, lane = tid & 31;
    int gid = lane >> 2, tig = lane & 3;

    __shared__ __align__(16) __nv_bfloat16 Ft_s[2][2][64][80];  // 2 buf x 2 sub, 160B rows
    __shared__ __align__(16) float2 FHs[2][128];
    __shared__ float Rs[128];

    int r0 = wid * 16 + gid, r1 = r0 + 8;
    float2 eg0 = g_EG1[h * Nn + i0 + r0];
    float2 eg1 = g_EG1[h * Nn + i0 + r1];
    float c[9][4] = {};
    uint32_t bones = (gid == 0) ? 0x3F803F80u : 0u;   // ones-column B fragment

    const float2* fhsrc = g_FH1 + h * Nn;
    const uint4* adj0 = (const uint4*)(g_adj + (size_t)(i0 + r0) * WPR);
    const uint4* adj1 = (const uint4*)(g_adj + (size_t)(i0 + r1) * WPR);

    auto stage = [&](int jt2, int buf) {
        const char* fbase = (const char*)g_ftb + ((size_t)(h * 64 + jt2 * 2)) * 8192;
#pragma unroll
        for (int r = 0; r < 4; ++r) {
            int cidx = tid + r * 256;
            int sub = cidx >> 9, cin = cidx & 511;
            cp16(&Ft_s[buf][sub][cin >> 3][(cin & 7) * 8], fbase + cidx * 16);
        }
        if (tid < 64) cp16(&FHs[buf][tid * 2], fhsrc + jt2 * 128 + tid * 2);
        cp_commit();
    };

    uint4 a0n = adj0[0], a1n = adj1[0];
    stage(0, 0);
    for (int jt2 = 0; jt2 < Nn / 128; ++jt2) {
        int buf = jt2 & 1;
        cp_wait_all();
        __syncthreads();
        if (jt2 + 1 < Nn / 128) stage(jt2 + 1, buf ^ 1);

        uint4 ca0 = a0n, ca1 = a1n;
        if (jt2 + 1 < Nn / 128) { a0n = adj0[jt2 + 1]; a1n = adj1[jt2 + 1]; }

#pragma unroll
        for (int sub = 0; sub < 2; ++sub) {
            unsigned wa0 = sub ? ca0.z : ca0.x, wb0 = sub ? ca0.w : ca0.y;
            unsigned wa1 = sub ? ca1.z : ca1.x, wb1 = sub ? ca1.w : ca1.y;
            const char* fsbase = (const char*)&Ft_s[buf][sub][0][0];
            const float2* fhb = &FHs[buf][sub * 64];
#pragma unroll
            for (int ks = 0; ks < 4; ++ks) {
                int jb2 = ks * 16;
                unsigned sw0 = ((ks & 2) ? wb0 : wa0) >> ((ks & 1) * 16);
                unsigned sw1 = ((ks & 2) ? wb1 : wa1) >> ((ks & 1) * 16);
                int j0 = 2 * tig, j2 = j0 + 8;
                float4 fA = *(const float4*)&fhb[jb2 + j0];   // F0,H0,F1,H1
                float4 fB = *(const float4*)&fhb[jb2 + j2];
                float p00 = fmaxf(eg0.x * fA.x, eg0.y * fA.y);
                float p01 = fmaxf(eg0.x * fA.z, eg0.y * fA.w);
                float p02 = fmaxf(eg0.x * fB.x, eg0.y * fB.y);
                float p03 = fmaxf(eg0.x * fB.z, eg0.y * fB.w);
                float p10 = fmaxf(eg1.x * fA.x, eg1.y * fA.y);
                float p11 = fmaxf(eg1.x * fA.z, eg1.y * fA.w);
                float p12 = fmaxf(eg1.x * fB.x, eg1.y * fB.y);
                float p13 = fmaxf(eg1.x * fB.z, eg1.y * fB.w);
                uint32_t a0 = pack_bf16x2(p00, p01) & bitmask2(sw0 >> j0);
                uint32_t a1 = pack_bf16x2(p10, p11) & bitmask2(sw1 >> j0);
                uint32_t a2 = pack_bf16x2(p02, p03) & bitmask2(sw0 >> j2);
                uint32_t a3 = pack_bf16x2(p12, p13) & bitmask2(sw1 >> j2);
#pragma unroll
                for (int nt = 0; nt < 8; ++nt) {
                    uint2 bb = *(const uint2*)(fsbase + (nt * 8 + gid) * 160 + ks * 32 + tig * 8);
                    mma_bf16(c[nt], a0, a1, a2, a3, bb.x, bb.y);
                }
                mma_bf16(c[8], a0, a1, a2, a3, bones, bones);   // rowsum column
            }
        }
    }
    if (tig == 0) { Rs[r0] = c[8][0]; Rs[r1] = c[8][2]; }
    __syncthreads();

    float inv0 = 1.0f / Rs[r0];
    float inv1 = 1.0f / Rs[r1];
    const float* bh = b1 + h * NH;
    float* d0 = g_h + (size_t)(i0 + r0) * (H1 * NH) + h * NH;
    float* d1 = g_h + (size_t)(i0 + r1) * (H1 * NH) + h * NH;
#pragma unroll
    for (int nt = 0; nt < 8; ++nt) {
        int cc = nt * 8 + 2 * tig;
        float2 bb = *(const float2*)(bh + cc);
        *(float2*)(d0 + cc) = make_float2(fmaxf(c[nt][0] * inv0 + bb.x, 0.f),
                                          fmaxf(c[nt][1] * inv0 + bb.y, 0.f));
        *(float2*)(d1 + cc) = make_float2(fmaxf(c[nt][2] * inv1 + bb.x, 0.f),
                                          fmaxf(c[nt][3] * inv1 + bb.y, 0.f));
    }
}

// ---------------- K4: feats2 = h @ W2 (K-split x8); factorized exps ------------
__global__ void k_gemm2(const float* __restrict__ W2, const float* __restrict__ as2,
                        const float* __restrict__ an2) {
    __shared__ float Ws[NF * NC];
    int tid = threadIdx.x;
    for (int u = tid; u < NF * NC; u += 256) Ws[u] = W2[u];
    __syncthreads();
    int row = blockIdx.x * 32 + (tid >> 3);
    int sl = tid & 7;
    const float* hr = g_h + (size_t)row * NF + sl * 64;
    float acc[NC] = {};
    for (int k = 0; k < 64; k += 4) {
        float4 xv = *(const float4*)&hr[k];
        const float* wp = &Ws[(sl * 64 + k) * NC];
#pragma unroll
        for (int f = 0; f < NC; ++f) {
            acc[f] = fmaf(xv.x, wp[f], acc[f]);
            acc[f] = fmaf(xv.y, wp[NC + f], acc[f]);
            acc[f] = fmaf(xv.z, wp[2 * NC + f], acc[f]);
            acc[f] = fmaf(xv.w, wp[3 * NC + f], acc[f]);
        }
    }
#pragma unroll
    for (int o = 4; o; o >>= 1)
#pragma unroll
        for (int f = 0; f < NC; ++f)
            acc[f] += __shfl_xor_sync(0xffffffffu, acc[f], o);
    if (sl == 0) {
        float sv = 0.f, nv = 0.f;
#pragma unroll
        for (int f = 0; f < NC; ++f) { sv = fmaf(acc[f], as2[f], sv); nv = fmaf(acc[f], an2[f], nv); }
        float4* fo = (float4*)&g_feats2[(size_t)row * NC];
        fo[0] = make_float4(acc[0], acc[1], acc[2], acc[3]);
        fo[1] = make_float4(acc[4], acc[5], acc[6], acc[7]);
        fo[2] = make_float4(acc[8], acc[9], acc[10], acc[11]);
        fo[3] = make_float4(acc[12], acc[13], acc[14], acc[15]);
        g_EG2[row] = make_float2(__expf(sv), __expf(0.2f * sv));
        g_FH2[row] = make_float2(__expf(nv), __expf(0.2f * nv));
    }
}

// ---------------- K5: layer-2 attention + relu + log_softmax -------------------
__global__ void k_attn2(const float* __restrict__ b2, float* __restrict__ out) {
    int i0 = blockIdx.x * 32;
    int tid = threadIdx.x;
    __shared__ float Ps[64][36];
    __shared__ __align__(16) float Fs[64][16];
    __shared__ float2 fhs[64];
    __shared__ float RsP[32][8];
    int pr = tid >> 3, pj = tid & 7;
    int irow = i0 + pr;
    float2 eg = g_EG2[irow];
    const unsigned* bi = g_adj + (size_t)irow * WPR;
    int tx = tid & 15, tq = tid >> 4;
    float acc0 = 0.f, acc1 = 0.f, rs = 0.f;

    for (int jt = 0; jt < Nn / 64; ++jt) {
        __syncthreads();
        ((float4*)&Fs[0][0])[tid] = ((const float4*)(g_feats2 + (size_t)jt * 64 * NC))[tid];
        if (tid < 64) fhs[tid] = g_FH2[jt * 64 + tid];
        __syncthreads();
        unsigned w0 = bi[jt * 2], w1 = bi[jt * 2 + 1];
#pragma unroll
        for (int k = 0; k < 8; ++k) {
            int j = pj + k * 8;
            unsigned bit = (j < 32) ? ((w0 >> j) & 1u) : ((w1 >> (j - 32)) & 1u);
            float2 fh = fhs[j];
            float p = bit ? fmaxf(eg.x * fh.x, eg.y * fh.y) : 0.f;
            rs += p;
            Ps[j][pr] = p;
        }
        __syncthreads();
#pragma unroll 8
        for (int j = 0; j < 64; ++j) {
            float b = Fs[j][tx];
            acc0 = fmaf(Ps[j][tq * 2], b, acc0);
            acc1 = fmaf(Ps[j][tq * 2 + 1], b, acc1);
        }
    }
    __syncthreads();
    RsP[pr][pj] = rs;
    __syncthreads();
    float s0 = 0.f, s1 = 0.f;
#pragma unroll
    for (int k = 0; k < 8; ++k) { s0 += RsP[tq * 2][k]; s1 += RsP[tq * 2 + 1][k]; }
    float bb = b2[tx];
    float v0 = fmaxf(acc0 / s0 + bb, 0.f);
    float v1 = fmaxf(acc1 / s1 + bb, 0.f);
    float m0 = v0, m1 = v1;
#pragma unroll
    for (int o = 8; o; o >>= 1) {
        m0 = fmaxf(m0, __shfl_xor_sync(0xffffffffu, m0, o));
        m1 = fmaxf(m1, __shfl_xor_sync(0xffffffffu, m1, o));
    }
    float e0 = __expf(v0 - m0), e1 = __expf(v1 - m1);
#pragma unroll
    for (int o = 8; o; o >>= 1) {
        e0 += __shfl_xor_sync(0xffffffffu, e0, o);
        e1 += __shfl_xor_sync(0xffffffffu, e1, o);
    }
    out[(size_t)(i0 + tq * 2 + 0) * NC + tx] = v0 - (logf(e0) + m0);
    out[(size_t)(i0 + tq * 2 + 1) * NC + tx] = v1 - (logf(e1) + m1);
}

// ---------------- launcher ----------------
extern "C" void kernel_launch(void* const* d_in, const int* in_sizes, int n_in,
                              void* d_out, int out_size) {
    (void)in_sizes; (void)n_in; (void)out_size;
    const float* x   = (const float*)d_in[0];
    const int*   adj = (const int*)d_in[1];
    const float* W1  = (const float*)d_in[2];
    const float* b1  = (const float*)d_in[3];
    const float* as1 = (const float*)d_in[4];
    const float* an1 = (const float*)d_in[5];
    const float* W2  = (const float*)d_in[6];
    const float* b2  = (const float*)d_in[7];
    const float* as2 = (const float*)d_in[8];
    const float* an2 = (const float*)d_in[9];
    float* out = (float*)d_out;

    k_prep<<<2048 + 256, 256>>>(adj, W1);                    // 1
    k_gemm1_mma<<<dim3(Nn / 128, H1), 256>>>(x, as1, an1);   // 2 (ftb + EG/FH fused)
    k_attn1_mma<<<dim3(Nn / 128, H1), 256>>>(b1);            // 3
    k_gemm2<<<Nn / 32, 256>>>(W2, as2, an2);                 // 4
    k_attn2<<<Nn / 32, 256>>>(b2, out);                      // 5
}

// round 13
// speedup vs baseline: 1.2755x; 1.1197x over previous
#include <cuda_runtime.h>
#include <cuda_bf16.h>
#include <cstdint>

#define Nn 4096
#define NF 512
#define NH 64
#define H1 8
#define NC 16
#define WPR 128   // words per adjacency row (4096/32)

// ---------------- scratch (static device globals; no allocation) ----------------
__device__ __align__(16) unsigned g_adj[Nn * WPR];            // 2 MB bitmask
// g_ftb: MMA-staged layout: [h][jt(64)][f(64)][64 j, pair-permuted] bf16
__device__ __align__(16) __nv_bfloat16 g_ftb[H1 * NH * Nn];   // 4 MB
__device__ __align__(16) float g_wt[H1 * NH * NF];            // 1 MB  [h][f][k]
__device__ __align__(16) float2 g_EG1[H1 * Nn];               // (exp(s), exp(.2 s))
__device__ __align__(16) float2 g_FH1[H1 * Nn];               // (exp(nb), exp(.2 nb))
__device__ __align__(16) float g_h[Nn * (H1 * NH)];           // 8 MB
__device__ __align__(16) float g_feats2[Nn * NC];
__device__ __align__(16) float2 g_EG2[Nn];
__device__ __align__(16) float2 g_FH2[Nn];

// ---------------- helpers ----------------
__device__ __forceinline__ uint32_t tf32r(float f) {
    uint32_t r; asm("cvt.rna.tf32.f32 %0, %1;" : "=r"(r) : "f"(f)); return r;
}
__device__ __forceinline__ float tf32f(float f) {
    uint32_t r = tf32r(f); return __uint_as_float(r);
}
__device__ __forceinline__ void mma_tf32(float* c,
                                         uint32_t a0, uint32_t a1, uint32_t a2, uint32_t a3,
                                         uint32_t b0, uint32_t b1) {
    asm volatile(
        "mma.sync.aligned.m16n8k8.row.col.f32.tf32.tf32.f32 "
        "{%0,%1,%2,%3}, {%4,%5,%6,%7}, {%8,%9}, {%0,%1,%2,%3};"
        : "+f"(c[0]), "+f"(c[1]), "+f"(c[2]), "+f"(c[3])
        : "r"(a0), "r"(a1), "r"(a2), "r"(a3), "r"(b0), "r"(b1));
}
__device__ __forceinline__ void mma_bf16(float* c,
                                         uint32_t a0, uint32_t a1, uint32_t a2, uint32_t a3,
                                         uint32_t b0, uint32_t b1) {
    asm volatile(
        "mma.sync.aligned.m16n8k16.row.col.f32.bf16.bf16.f32 "
        "{%0,%1,%2,%3}, {%4,%5,%6,%7}, {%8,%9}, {%0,%1,%2,%3};"
        : "+f"(c[0]), "+f"(c[1]), "+f"(c[2]), "+f"(c[3])
        : "r"(a0), "r"(a1), "r"(a2), "r"(a3), "r"(b0), "r"(b1));
}
__device__ __forceinline__ uint32_t pack_bf16x2(float lo, float hi) {
    uint32_t d;
    asm("cvt.rn.bf16x2.f32 %0, %1, %2;" : "=r"(d) : "f"(hi), "f"(lo));
    return d;
}
__device__ __forceinline__ void cp16(void* dst, const void* src) {
    uint32_t d = (uint32_t)__cvta_generic_to_shared(dst);
    asm volatile("cp.async.cg.shared.global [%0], [%1], 16;" :: "r"(d), "l"(src) : "memory");
}
__device__ __forceinline__ void cp_commit() {
    asm volatile("cp.async.commit_group;" ::: "memory");
}
__device__ __forceinline__ void cp_wait_all() {
    asm volatile("cp.async.wait_group 0;" ::: "memory");
}
// bf16x2 AND-mask from 2 adjacent adjacency bits in t (bit0 -> low half, bit1 -> high)
__device__ __forceinline__ uint32_t bitmask2(unsigned t) {
    return (t & 1u) * 0xFFFFu + (t & 2u) * 0x7FFF8000u;
}

// ---------------- K1: prep = adjacency bitmask + W1 transpose/round ------------
__global__ void k_prep(const int* __restrict__ adj, const float* __restrict__ W1) {
    __shared__ float t[32][33];
    if (blockIdx.x < 2048) {
        int gw = blockIdx.x * 8 + (threadIdx.x >> 5);
        int lane = threadIdx.x & 31;
        int row = gw >> 2, q = gw & 3;
        const int* base = adj + (size_t)row * Nn + q * 1024;
        unsigned* wbase = g_adj + row * WPR + q * 32;
#pragma unroll 4
        for (int w = 0; w < 32; ++w) {
            unsigned m = __ballot_sync(0xffffffffu, base[w * 32 + lane] > 0);
            if (lane == 0) wbase[w] = m;
        }
    } else {
        int idx = blockIdx.x - 2048;           // 0..255
        int h = idx >> 5;
        int r = idx & 31;
        int kt = (r >> 1) * 32, ft = (r & 1) * 32;
        int x = threadIdx.x & 31, y = threadIdx.x >> 5;
        const float* src = W1 + (size_t)h * NF * NH;
#pragma unroll
        for (int rr = y; rr < 32; rr += 8)
            t[rr][x] = src[(size_t)(kt + rr) * NH + ft + x];
        __syncthreads();
        float* dst = g_wt + (size_t)h * NH * NF;
#pragma unroll
        for (int rr = y; rr < 32; rr += 8)
            dst[(size_t)(ft + rr) * NF + kt + x] = tf32f(t[x][rr]);
    }
}

// ---------------- K2: gemm1 + fused ftb-permute + EG/FH epilogue ---------------
__global__ void __launch_bounds__(256, 2) k_gemm1_mma(const float* __restrict__ x,
                                                      const float* __restrict__ as1,
                                                      const float* __restrict__ an1) {
    int h = blockIdx.y;
    int i0 = blockIdx.x * 128;
    int tid = threadIdx.x, wid = tid >> 5, lane = tid & 31;
    int gid = lane >> 2, tig = lane & 3;
    __shared__ float Xs[128][40];    // 160B rows
    __shared__ float Wt_s[64][40];
    __shared__ __align__(16) float avs[64], nvs[64];

    if (tid < 64) { avs[tid] = as1[h * NH + tid]; nvs[tid] = an1[h * NH + tid]; }

    int r0 = wid * 16 + gid, r1 = r0 + 8;
    float c[8][4] = {};

    int srow = tid >> 1, shalf = tid & 1;
    int sf = tid >> 2, sq = tid & 3;
    const float* xsrc = x + (size_t)(i0 + srow) * NF + shalf * 16;
    const float* wsrc = g_wt + ((size_t)h * NH + sf) * NF + sq * 8;

    for (int kc = 0; kc < NF / 32; ++kc) {
        __syncthreads();
#pragma unroll
        for (int v = 0; v < 4; ++v) {
            float4 t = *(const float4*)(xsrc + kc * 32 + v * 4);
            t.x = tf32f(t.x); t.y = tf32f(t.y); t.z = tf32f(t.z); t.w = tf32f(t.w);
            *(float4*)&Xs[srow][shalf * 16 + v * 4] = t;
        }
        {
            float4 v0 = *(const float4*)(wsrc + kc * 32);
            float4 v1 = *(const float4*)(wsrc + kc * 32 + 4);
            *(float4*)&Wt_s[sf][sq * 8] = v0;
            *(float4*)&Wt_s[sf][sq * 8 + 4] = v1;
        }
        __syncthreads();
#pragma unroll
        for (int ks = 0; ks < 4; ++ks) {
            int k0 = ks * 8 + 2 * tig;
            float2 a02 = *(const float2*)&Xs[r0][k0];
            float2 a13 = *(const float2*)&Xs[r1][k0];
            uint32_t a0 = __float_as_uint(a02.x), a2 = __float_as_uint(a02.y);
            uint32_t a1 = __float_as_uint(a13.x), a3 = __float_as_uint(a13.y);
#pragma unroll
            for (int nt = 0; nt < 8; ++nt) {
                float2 b = *(const float2*)&Wt_s[nt * 8 + gid][k0];
                mma_tf32(c[nt], a0, a1, a2, a3, __float_as_uint(b.x), __float_as_uint(b.y));
            }
        }
    }

    // ---- fused epilogue 1: permuted bf16 g_ftb via shuffle pairing ----
    int jt = (i0 >> 6) + (wid >> 2);
    int jl0 = r0 & 63, jl1 = r1 & 63;
    int q0 = (jl0 & 15) >> 1, q1 = (jl1 & 15) >> 1;
    int w0o = (jl0 >> 4) * 8 + (q0 < 4 ? 2 * q0 : 2 * (q0 - 4) + 1);
    int w1o = (jl1 >> 4) * 8 + (q1 < 4 ? 2 * q1 : 2 * (q1 - 4) + 1);
    uint32_t* tbase = (uint32_t*)g_ftb + ((size_t)(h * 64 + jt) * 64) * 32;
    bool evengid = ((gid & 1) == 0);
#pragma unroll
    for (int nt = 0; nt < 8; ++nt) {
        float u0 = __shfl_down_sync(0xffffffffu, c[nt][0], 4);
        float u1 = __shfl_down_sync(0xffffffffu, c[nt][1], 4);
        float u2 = __shfl_down_sync(0xffffffffu, c[nt][2], 4);
        float u3 = __shfl_down_sync(0xffffffffu, c[nt][3], 4);
        if (evengid) {
            int f0 = nt * 8 + 2 * tig;
            tbase[(f0 + 0) * 32 + w0o] = pack_bf16x2(c[nt][0], u0);
            tbase[(f0 + 1) * 32 + w0o] = pack_bf16x2(c[nt][1], u1);
            tbase[(f0 + 0) * 32 + w1o] = pack_bf16x2(c[nt][2], u2);
            tbase[(f0 + 1) * 32 + w1o] = pack_bf16x2(c[nt][3], u3);
        }
    }
    // ---- fused epilogue 2: EG/FH per row ----
    float vs0 = 0.f, vn0 = 0.f, vs1 = 0.f, vn1 = 0.f;
#pragma unroll
    for (int nt = 0; nt < 8; ++nt) {
        int f0 = nt * 8 + 2 * tig;
        float2 av = *(const float2*)&avs[f0];
        float2 nv = *(const float2*)&nvs[f0];
        vs0 += c[nt][0] * av.x + c[nt][1] * av.y;
        vs1 += c[nt][2] * av.x + c[nt][3] * av.y;
        vn0 += c[nt][0] * nv.x + c[nt][1] * nv.y;
        vn1 += c[nt][2] * nv.x + c[nt][3] * nv.y;
    }
    vs0 += __shfl_xor_sync(0xffffffffu, vs0, 1); vs0 += __shfl_xor_sync(0xffffffffu, vs0, 2);
    vs1 += __shfl_xor_sync(0xffffffffu, vs1, 1); vs1 += __shfl_xor_sync(0xffffffffu, vs1, 2);
    vn0 += __shfl_xor_sync(0xffffffffu, vn0, 1); vn0 += __shfl_xor_sync(0xffffffffu, vn0, 2);
    vn1 += __shfl_xor_sync(0xffffffffu, vn1, 1); vn1 += __shfl_xor_sync(0xffffffffu, vn1, 2);
    if (tig == 0) {
        int gi0 = h * Nn + i0 + r0, gi1 = h * Nn + i0 + r1;
        g_EG1[gi0] = make_float2(__expf(vs0), __expf(0.2f * vs0));
        g_FH1[gi0] = make_float2(__expf(vn0), __expf(0.2f * vn0));
        g_EG1[gi1] = make_float2(__expf(vs1), __expf(0.2f * vs1));
        g_FH1[gi1] = make_float2(__expf(vn1), __expf(0.2f * vn1));
    }
}

// ---------------- K3: layer-1 attention, bf16 mma, 128-j chunks ----------------
__global__ void __launch_bounds__(256, 2) k_attn1_mma(const float* __restrict__ b1) {
    int h = blockIdx.y;
    int i0 = blockIdx.x * 128;
    int tid = threadIdx.x, wid = tid >> 5, lane = tid & 31;
    int gid = lane >> 2, tig = lane & 3;

    __shared__ __align__(16) __nv_bfloat16 Ft_s[2][2][64][80];  // 2 buf x 2 sub
    __shared__ __align__(16) float2 FHs[2][128];
    __shared__ float Rs[128];

    int r0 = wid * 16 + gid, r1 = r0 + 8;
    float2 eg0 = g_EG1[h * Nn + i0 + r0];
    float2 eg1 = g_EG1[h * Nn + i0 + r1];
    float c[9][4] = {};
    uint32_t bones = (gid == 0) ? 0x3F803F80u : 0u;   // ones-column B fragment

    const float2* fhsrc = g_FH1 + h * Nn;
    const uint4* adj0 = (const uint4*)(g_adj + (size_t)(i0 + r0) * WPR);
    const uint4* adj1 = (const uint4*)(g_adj + (size_t)(i0 + r1) * WPR);

    auto stage = [&](int jt2, int buf) {
        const char* fbase = (const char*)g_ftb + ((size_t)(h * 64 + jt2 * 2)) * 8192;
#pragma unroll
        for (int r = 0; r < 4; ++r) {
            int cidx = tid + r * 256;
            int sub = cidx >> 9, cin = cidx & 511;
            cp16(&Ft_s[buf][sub][cin >> 3][(cin & 7) * 8], fbase + cidx * 16);
        }
        if (tid < 64) cp16(&FHs[buf][tid * 2], fhsrc + jt2 * 128 + tid * 2);
        cp_commit();
    };

    uint4 a0n = adj0[0], a1n = adj1[0];
    stage(0, 0);
    for (int jt2 = 0; jt2 < Nn / 128; ++jt2) {
        int buf = jt2 & 1;
        cp_wait_all();
        __syncthreads();
        if (jt2 + 1 < Nn / 128) stage(jt2 + 1, buf ^ 1);

        uint4 ca0 = a0n, ca1 = a1n;
        if (jt2 + 1 < Nn / 128) { a0n = adj0[jt2 + 1]; a1n = adj1[jt2 + 1]; }

#pragma unroll
        for (int sub = 0; sub < 2; ++sub) {
            unsigned wa0 = sub ? ca0.z : ca0.x, wb0 = sub ? ca0.w : ca0.y;
            unsigned wa1 = sub ? ca1.z : ca1.x, wb1 = sub ? ca1.w : ca1.y;
            const char* fsbase = (const char*)&Ft_s[buf][sub][0][0];
            const float2* fhb = &FHs[buf][sub * 64];
#pragma unroll
            for (int ks = 0; ks < 4; ++ks) {
                int jb2 = ks * 16;
                unsigned sw0 = ((ks & 2) ? wb0 : wa0) >> ((ks & 1) * 16);
                unsigned sw1 = ((ks & 2) ? wb1 : wa1) >> ((ks & 1) * 16);
                int j0 = 2 * tig, j2 = j0 + 8;
                float4 fA = *(const float4*)&fhb[jb2 + j0];
                float4 fB = *(const float4*)&fhb[jb2 + j2];
                float p00 = fmaxf(eg0.x * fA.x, eg0.y * fA.y);
                float p01 = fmaxf(eg0.x * fA.z, eg0.y * fA.w);
                float p02 = fmaxf(eg0.x * fB.x, eg0.y * fB.y);
                float p03 = fmaxf(eg0.x * fB.z, eg0.y * fB.w);
                float p10 = fmaxf(eg1.x * fA.x, eg1.y * fA.y);
                float p11 = fmaxf(eg1.x * fA.z, eg1.y * fA.w);
                float p12 = fmaxf(eg1.x * fB.x, eg1.y * fB.y);
                float p13 = fmaxf(eg1.x * fB.z, eg1.y * fB.w);
                uint32_t a0 = pack_bf16x2(p00, p01) & bitmask2(sw0 >> j0);
                uint32_t a1 = pack_bf16x2(p10, p11) & bitmask2(sw1 >> j0);
                uint32_t a2 = pack_bf16x2(p02, p03) & bitmask2(sw0 >> j2);
                uint32_t a3 = pack_bf16x2(p12, p13) & bitmask2(sw1 >> j2);
#pragma unroll
                for (int nt = 0; nt < 8; ++nt) {
                    uint2 bb = *(const uint2*)(fsbase + (nt * 8 + gid) * 160 + ks * 32 + tig * 8);
                    mma_bf16(c[nt], a0, a1, a2, a3, bb.x, bb.y);
                }
                mma_bf16(c[8], a0, a1, a2, a3, bones, bones);   // rowsum column
            }
        }
    }
    if (tig == 0) { Rs[r0] = c[8][0]; Rs[r1] = c[8][2]; }
    __syncthreads();

    float inv0 = 1.0f / Rs[r0];
    float inv1 = 1.0f / Rs[r1];
    const float* bh = b1 + h * NH;
    float* d0 = g_h + (size_t)(i0 + r0) * (H1 * NH) + h * NH;
    float* d1 = g_h + (size_t)(i0 + r1) * (H1 * NH) + h * NH;
#pragma unroll
    for (int nt = 0; nt < 8; ++nt) {
        int cc = nt * 8 + 2 * tig;
        float2 bb = *(const float2*)(bh + cc);
        *(float2*)(d0 + cc) = make_float2(fmaxf(c[nt][0] * inv0 + bb.x, 0.f),
                                          fmaxf(c[nt][1] * inv0 + bb.y, 0.f));
        *(float2*)(d1 + cc) = make_float2(fmaxf(c[nt][2] * inv1 + bb.x, 0.f),
                                          fmaxf(c[nt][3] * inv1 + bb.y, 0.f));
    }
}

// ---------------- K4: feats2 = h @ W2 — warp-per-row, coalesced, conflict-free --
__global__ void __launch_bounds__(256) k_gemm2(const float* __restrict__ W2,
                                               const float* __restrict__ as2,
                                               const float* __restrict__ an2) {
    __shared__ float Wt[NC][520];          // [f][k], padded row (4-way store conflict only)
    __shared__ __align__(16) float as_s[NC], an_s[NC];
    int tid = threadIdx.x;
    for (int u = tid; u < NF * NC; u += 256) {
        int k = u >> 4, f = u & 15;
        Wt[f][k] = W2[u];
    }
    if (tid < NC) { as_s[tid] = as2[tid]; an_s[tid] = an2[tid]; }
    __syncthreads();

    int wid = tid >> 5, lane = tid & 31;
    int row = blockIdx.x * 8 + wid;
    const float* hr = g_h + (size_t)row * NF;
    float acc[NC] = {};
#pragma unroll
    for (int p = 0; p < 4; ++p) {
        float4 xv = *(const float4*)&hr[p * 128 + lane * 4];   // coalesced LDG.128
#pragma unroll
        for (int f = 0; f < NC; ++f) {
            float4 wv = *(const float4*)&Wt[f][p * 128 + lane * 4];  // conflict-free LDS.128
            acc[f] += xv.x * wv.x + xv.y * wv.y + xv.z * wv.z + xv.w * wv.w;
        }
    }
#pragma unroll
    for (int f = 0; f < NC; ++f) {
#pragma unroll
        for (int o = 16; o; o >>= 1)
            acc[f] += __shfl_xor_sync(0xffffffffu, acc[f], o);
    }
    if (lane == 0) {
        float sv = 0.f, nv = 0.f;
#pragma unroll
        for (int f = 0; f < NC; ++f) { sv = fmaf(acc[f], as_s[f], sv); nv = fmaf(acc[f], an_s[f], nv); }
        float4* fo = (float4*)&g_feats2[(size_t)row * NC];
        fo[0] = make_float4(acc[0], acc[1], acc[2], acc[3]);
        fo[1] = make_float4(acc[4], acc[5], acc[6], acc[7]);
        fo[2] = make_float4(acc[8], acc[9], acc[10], acc[11]);
        fo[3] = make_float4(acc[12], acc[13], acc[14], acc[15]);
        g_EG2[row] = make_float2(__expf(sv), __expf(0.2f * sv));
        g_FH2[row] = make_float2(__expf(nv), __expf(0.2f * nv));
    }
}

// ---------------- K5: layer-2 attention + relu + log_softmax -------------------
__global__ void k_attn2(const float* __restrict__ b2, float* __restrict__ out) {
    int i0 = blockIdx.x * 32;
    int tid = threadIdx.x;
    __shared__ float Ps[64][36];
    __shared__ __align__(16) float Fs[64][16];
    __shared__ float2 fhs[64];
    __shared__ float RsP[32][8];
    int pr = tid >> 3, pj = tid & 7;
    int irow = i0 + pr;
    float2 eg = g_EG2[irow];
    const unsigned* bi = g_adj + (size_t)irow * WPR;
    int tx = tid & 15, tq = tid >> 4;
    float acc0 = 0.f, acc1 = 0.f, rs = 0.f;

    for (int jt = 0; jt < Nn / 64; ++jt) {
        __syncthreads();
        ((float4*)&Fs[0][0])[tid] = ((const float4*)(g_feats2 + (size_t)jt * 64 * NC))[tid];
        if (tid < 64) fhs[tid] = g_FH2[jt * 64 + tid];
        __syncthreads();
        unsigned w0 = bi[jt * 2], w1 = bi[jt * 2 + 1];
#pragma unroll
        for (int k = 0; k < 8; ++k) {
            int j = pj + k * 8;
            unsigned bit = (j < 32) ? ((w0 >> j) & 1u) : ((w1 >> (j - 32)) & 1u);
            float2 fh = fhs[j];
            float p = bit ? fmaxf(eg.x * fh.x, eg.y * fh.y) : 0.f;
            rs += p;
            Ps[j][pr] = p;
        }
        __syncthreads();
#pragma unroll 8
        for (int j = 0; j < 64; ++j) {
            float b = Fs[j][tx];
            acc0 = fmaf(Ps[j][tq * 2], b, acc0);
            acc1 = fmaf(Ps[j][tq * 2 + 1], b, acc1);
        }
    }
    __syncthreads();
    RsP[pr][pj] = rs;
    __syncthreads();
    float s0 = 0.f, s1 = 0.f;
#pragma unroll
    for (int k = 0; k < 8; ++k) { s0 += RsP[tq * 2][k]; s1 += RsP[tq * 2 + 1][k]; }
    float bb = b2[tx];
    float v0 = fmaxf(acc0 / s0 + bb, 0.f);
    float v1 = fmaxf(acc1 / s1 + bb, 0.f);
    float m0 = v0, m1 = v1;
#pragma unroll
    for (int o = 8; o; o >>= 1) {
        m0 = fmaxf(m0, __shfl_xor_sync(0xffffffffu, m0, o));
        m1 = fmaxf(m1, __shfl_xor_sync(0xffffffffu, m1, o));
    }
    float e0 = __expf(v0 - m0), e1 = __expf(v1 - m1);
#pragma unroll
    for (int o = 8; o; o >>= 1) {
        e0 += __shfl_xor_sync(0xffffffffu, e0, o);
        e1 += __shfl_xor_sync(0xffffffffu, e1, o);
    }
    out[(size_t)(i0 + tq * 2 + 0) * NC + tx] = v0 - (logf(e0) + m0);
    out[(size_t)(i0 + tq * 2 + 1) * NC + tx] = v1 - (logf(e1) + m1);
}

// ---------------- launcher ----------------
extern "C" void kernel_launch(void* const* d_in, const int* in_sizes, int n_in,
                              void* d_out, int out_size) {
    (void)in_sizes; (void)n_in; (void)out_size;
    const float* x   = (const float*)d_in[0];
    const int*   adj = (const int*)d_in[1];
    const float* W1  = (const float*)d_in[2];
    const float* b1  = (const float*)d_in[3];
    const float* as1 = (const float*)d_in[4];
    const float* an1 = (const float*)d_in[5];
    const float* W2  = (const float*)d_in[6];
    const float* b2  = (const float*)d_in[7];
    const float* as2 = (const float*)d_in[8];
    const float* an2 = (const float*)d_in[9];
    float* out = (float*)d_out;

    k_prep<<<2048 + 256, 256>>>(adj, W1);                    // 1
    k_gemm1_mma<<<dim3(Nn / 128, H1), 256>>>(x, as1, an1);   // 2 (ftb + EG/FH fused)
    k_attn1_mma<<<dim3(Nn / 128, H1), 256>>>(b1);            // 3
    k_gemm2<<<Nn / 8, 256>>>(W2, as2, an2);                  // 4
    k_attn2<<<Nn / 32, 256>>>(b2, out);                      // 5
}